// round 1
// baseline (speedup 1.0000x reference)
#include <cuda_runtime.h>
#include <math.h>

#define Xd 32
#define Yd 16
#define Zd 16
#define Nn 8192          // X*Y*Z
#define Cc 4
#define NITER 5
#define ALPHA 5.0f
#define BETA  5.0f
#define GAMMA 5.0f
#define W1c 1.0f
#define W2c 1.0f

// ---- scratch (static device memory; no allocations anywhere) ----
__device__ float  g_M[(size_t)Nn * (size_t)Nn];   // 256 MiB combined filter matrix
__device__ float4 g_feat[Nn];                     // (fa, fb, e_m, 0)
__device__ float4 g_P[Nn];                        // (fa, fb, a*e, b)
__device__ float  g_rs1[Nn];                      // bilateral row sums
__device__ float4 g_qA[Nn];                       // q ping  (node-major, 4 channels)
__device__ float4 g_qB[Nn];                       // q pong
__device__ float  g_ax[Xd], g_ay[Yd], g_az[Zd];   // alpha (bilateral spatial) tables
__device__ float  g_gx[Xd], g_gy[Yd], g_gz[Zd];   // gamma (spatial) tables
__device__ float  g_Rx[Xd], g_Ry[Yd], g_Rz[Zd];   // spatial-filter rowsum factors

// ---------------------------------------------------------------- setup tables
__global__ void k_tables() {
    int t = threadIdx.x;
    if (t < Xd) {
        float d = (float)t;
        g_ax[t] = __expf(-0.5f * d * d / (ALPHA * ALPHA));
        g_gx[t] = __expf(-0.5f * d * d / (GAMMA * GAMMA));
    }
    if (t < Yd) {
        float d = (float)t;
        float a = __expf(-0.5f * d * d / (ALPHA * ALPHA));
        float g = __expf(-0.5f * d * d / (GAMMA * GAMMA));
        g_ay[t] = a; g_az[t] = a;
        g_gy[t] = g; g_gz[t] = g;
    }
    __syncthreads();
    if (t < Xd) {
        float s = 0.f;
        for (int x = 0; x < Xd; x++) s += g_gx[abs(t - x)];
        g_Rx[t] = s;
    }
    if (t < Yd) {
        float sy = 0.f, sz = 0.f;
        for (int y = 0; y < Yd; y++) { sy += g_gy[abs(t - y)]; sz += g_gz[abs(t - y)]; }
        g_Ry[t] = sy; g_Rz[t] = sz;
    }
}

// ---------------------------------------------------------- features + q0=softmax(lu)
__global__ void k_feat_q0(const float* __restrict__ lu, const float* __restrict__ fp) {
    int n = blockIdx.x * blockDim.x + threadIdx.x;
    if (n >= Nn) return;
    float fa = fp[n]        * (1.0f / BETA);
    float fb = fp[Nn + n]   * (1.0f / BETA);
    float e  = __expf(-0.5f * (fa * fa + fb * fb));
    g_feat[n] = make_float4(fa, fb, e, 0.f);

    float l0 = lu[0 * Nn + n], l1 = lu[1 * Nn + n];
    float l2 = lu[2 * Nn + n], l3 = lu[3 * Nn + n];
    float mx = fmaxf(fmaxf(l0, l1), fmaxf(l2, l3));
    float e0 = __expf(l0 - mx), e1 = __expf(l1 - mx);
    float e2 = __expf(l2 - mx), e3 = __expf(l3 - mx);
    float inv = 1.0f / (e0 + e1 + e2 + e3);
    g_qA[n] = make_float4(e0 * inv, e1 * inv, e2 * inv, e3 * inv);
}

// --------------------------------------------------- bilateral row sums (no stores)
__global__ void k_rowsum() {
    __shared__ float sax[Xd], say[Yd], saz[Zd];
    int tid = threadIdx.x;
    if (tid < Xd) sax[tid] = g_ax[tid];
    if (tid < Yd) { say[tid] = g_ay[tid]; saz[tid] = g_az[tid]; }
    __syncthreads();

    int warp = tid >> 5, lane = tid & 31;
    int n = blockIdx.x * 8 + warp;
    float4 fn = g_feat[n];
    int xn = n >> 8, yn = (n >> 4) & 15, zn = n & 15;

    float sum = 0.f;
    for (int m4 = lane; m4 < Nn / 4; m4 += 32) {
        int m = m4 << 2;
        int xm = m >> 8, ym = (m >> 4) & 15, zm = m & 15;  // 4 consecutive m share x,y
        float sA = sax[abs(xn - xm)] * say[abs(yn - ym)] * fn.z;
        const float4* fp4 = g_feat + m;
#pragma unroll
        for (int i = 0; i < 4; i++) {
            float4 F = fp4[i];
            float arg = fn.x * F.x + fn.y * F.y;
            sum += sA * saz[abs(zn - (zm + i))] * F.z * __expf(arg);
        }
    }
#pragma unroll
    for (int o = 16; o; o >>= 1) sum += __shfl_xor_sync(0xFFFFFFFFu, sum, o);
    if (lane == 0) g_rs1[n] = sum;
}

// ------------------------------------------------------------------- pack scales
__global__ void k_scales() {
    int n = blockIdx.x * blockDim.x + threadIdx.x;
    if (n >= Nn) return;
    float a = sqrtf(W1c) * rsqrtf(g_rs1[n]);
    float b = sqrtf(W2c) * rsqrtf(g_Rx[n >> 8] * g_Ry[(n >> 4) & 15] * g_Rz[n & 15]);
    float4 f = g_feat[n];
    g_P[n] = make_float4(f.x, f.y, a * f.z, b);
}

// -------------------------------------------------------------- build combined M
__global__ void k_build() {
    __shared__ float sax[Xd], say[Yd], saz[Zd];
    __shared__ float sgx[Xd], sgy[Yd], sgz[Zd];
    int tid = threadIdx.x;
    if (tid < Xd) { sax[tid] = g_ax[tid]; sgx[tid] = g_gx[tid]; }
    if (tid < Yd) { say[tid] = g_ay[tid]; saz[tid] = g_az[tid];
                    sgy[tid] = g_gy[tid]; sgz[tid] = g_gz[tid]; }
    __syncthreads();

    int warp = tid >> 5, lane = tid & 31;
    int n = blockIdx.x * 8 + warp;
    float4 Pn = g_P[n];
    int xn = n >> 8, yn = (n >> 4) & 15, zn = n & 15;
    float4* Mrow = (float4*)(g_M + (size_t)n * Nn);

    for (int m4 = lane; m4 < Nn / 4; m4 += 32) {
        int m = m4 << 2;
        int xm = m >> 8, ym = (m >> 4) & 15, zm = m & 15;
        int dx = abs(xn - xm), dy = abs(yn - ym);
        float sA = sax[dx] * say[dy] * Pn.z;   // includes a_n * e_n
        float sG = sgx[dx] * sgy[dy] * Pn.w;   // includes b_n
        const float4* pp4 = g_P + m;
        float4 out;
        float v[4];
#pragma unroll
        for (int i = 0; i < 4; i++) {
            float4 F = pp4[i];
            int dz = abs(zn - (zm + i));
            float arg = Pn.x * F.x + Pn.y * F.y;
            v[i] = sA * saz[dz] * F.z * __expf(arg) + sG * sgz[dz] * F.w;
        }
        out.x = v[0]; out.y = v[1]; out.z = v[2]; out.w = v[3];
        Mrow[m4] = out;
    }
}

// --------------------------------------------------------------- one CRF iteration
__global__ void k_iter(const float* __restrict__ lu, const float* __restrict__ comp,
                       int dir) {
    __shared__ float scomp[16];
    int tid = threadIdx.x;
    if (tid < 16) scomp[tid] = comp[tid];
    __syncthreads();

    const float4* __restrict__ qIn  = dir ? g_qB : g_qA;
    float4* __restrict__       qOut = dir ? g_qA : g_qB;

    int warp = tid >> 5, lane = tid & 31;
    int n = blockIdx.x * 8 + warp;
    const float4* Mrow = (const float4*)(g_M + (size_t)n * Nn);

    float a0 = 0.f, a1 = 0.f, a2 = 0.f, a3 = 0.f;
    for (int m4 = lane; m4 < Nn / 4; m4 += 32) {
        float4 mv = Mrow[m4];
        const float4* qp = qIn + (m4 << 2);
        float4 q0 = qp[0], q1 = qp[1], q2 = qp[2], q3 = qp[3];
        a0 += mv.x * q0.x + mv.y * q1.x + mv.z * q2.x + mv.w * q3.x;
        a1 += mv.x * q0.y + mv.y * q1.y + mv.z * q2.y + mv.w * q3.y;
        a2 += mv.x * q0.z + mv.y * q1.z + mv.z * q2.z + mv.w * q3.z;
        a3 += mv.x * q0.w + mv.y * q1.w + mv.z * q2.w + mv.w * q3.w;
    }
#pragma unroll
    for (int o = 16; o; o >>= 1) {
        a0 += __shfl_xor_sync(0xFFFFFFFFu, a0, o);
        a1 += __shfl_xor_sync(0xFFFFFFFFu, a1, o);
        a2 += __shfl_xor_sync(0xFFFFFFFFu, a2, o);
        a3 += __shfl_xor_sync(0xFFFFFFFFu, a3, o);
    }
    // every lane has the full sums; compute compat + softmax redundantly, lane 0 writes
    float qc[4] = {a0, a1, a2, a3};
    float lg[4];
#pragma unroll
    for (int o = 0; o < 4; o++) {
        float qu = scomp[o * 4 + 0] * qc[0] + scomp[o * 4 + 1] * qc[1]
                 + scomp[o * 4 + 2] * qc[2] + scomp[o * 4 + 3] * qc[3];
        lg[o] = lu[o * Nn + n] - qu;
    }
    float mx = fmaxf(fmaxf(lg[0], lg[1]), fmaxf(lg[2], lg[3]));
    float e0 = __expf(lg[0] - mx), e1 = __expf(lg[1] - mx);
    float e2 = __expf(lg[2] - mx), e3 = __expf(lg[3] - mx);
    float inv = 1.0f / (e0 + e1 + e2 + e3);
    if (lane == 0) qOut[n] = make_float4(e0 * inv, e1 * inv, e2 * inv, e3 * inv);
}

// ---------------------------------------------------------------- write output
__global__ void k_out(float* __restrict__ out) {
    int t = blockIdx.x * blockDim.x + threadIdx.x;
    if (t >= Cc * Nn) return;
    int c = t >> 13;         // t / 8192
    int n = t & (Nn - 1);
    // NITER=5 (odd): final q lives in g_qB
    out[t] = ((const float*)g_qB)[n * 4 + c];
}

extern "C" void kernel_launch(void* const* d_in, const int* in_sizes, int n_in,
                              void* d_out, int out_size) {
    const float* lu   = (const float*)d_in[0];
    const float* fp   = (const float*)d_in[1];
    const float* comp = (const float*)d_in[2];
    float* out = (float*)d_out;

    k_tables<<<1, 64>>>();
    k_feat_q0<<<Nn / 256, 256>>>(lu, fp);
    k_rowsum<<<Nn / 8, 256>>>();
    k_scales<<<Nn / 256, 256>>>();
    k_build<<<Nn / 8, 256>>>();
    for (int i = 0; i < NITER; i++)
        k_iter<<<Nn / 8, 256>>>(lu, comp, i & 1);
    k_out<<<(Cc * Nn) / 256, 256>>>(out);
}

// round 2
// speedup vs baseline: 7.8930x; 7.8930x over previous
#include <cuda_runtime.h>
#include <math.h>

#define Xd 32
#define Yd 16
#define Nn 8192          // 32*16*16
#define Cc 4
#define NITER 5
#define ALPHA 5.0f
#define BETA  5.0f
#define GAMMA 5.0f
#define W1c 1.0f
#define W2c 1.0f
#define DEG 8            // total-degree Taylor truncation for exp(f.f')
#define RK 45            // number of (i,j), i+j<=8
#define NBLK (RK * Cc + Cc)          // 184: bilateral ranks x channels + spatial x channels
#define SMEM_BYTES ((2 * Nn + Xd + Yd) * 4)

// ---- static device scratch (no allocations anywhere) ----
__device__ float g_phi[RK][Nn];      // rank basis functions
__device__ float g_e[Nn];            // exp(-|f|^2/2)
__device__ float g_pre1[Nn];         // sqrt(W1) * e * s1
__device__ float g_pre2[Nn];         // sqrt(W2) * s2
__device__ float g_part[NBLK][Nn];   // per-(rank,channel) partial filter outputs
__device__ float g_qp[2][Cc][Nn];    // q ping-pong, planar per channel
__device__ float g_ax[Xd], g_ayz[Yd], g_gx[Xd], g_gyz[Yd];  // 1-D Gaussian tables
__device__ float g_Rx[Xd], g_Ryz[Yd];                        // spatial rowsum factors

// ------------------------------------------------------------------ tables
__global__ void k_tables() {
    int t = threadIdx.x;
    if (t < Xd) {
        float d = (float)t;
        g_ax[t] = __expf(-0.5f * d * d / (ALPHA * ALPHA));
        g_gx[t] = __expf(-0.5f * d * d / (GAMMA * GAMMA));
    }
    if (t < Yd) {
        float d = (float)t;
        g_ayz[t] = __expf(-0.5f * d * d / (ALPHA * ALPHA));
        g_gyz[t] = __expf(-0.5f * d * d / (GAMMA * GAMMA));
    }
    __syncthreads();
    if (t < Xd) {
        float s = 0.f;
        for (int x = 0; x < Xd; x++) s += g_gx[abs(t - x)];
        g_Rx[t] = s;
    }
    if (t < Yd) {
        float s = 0.f;
        for (int y = 0; y < Yd; y++) s += g_gyz[abs(t - y)];
        g_Ryz[t] = s;
    }
}

// ------------------------------------------- features, rank basis, q0 = softmax(lu)
__global__ void k_feat(const float* __restrict__ lu, const float* __restrict__ fp) {
    __shared__ float scoef[RK];
    int tid = threadIdx.x;
    if (tid == 0) {
        float fact[DEG + 1];
        fact[0] = 1.f;
        for (int i = 1; i <= DEG; i++) fact[i] = fact[i - 1] * (float)i;
        int r = 0;
        for (int i = 0; i <= DEG; i++)
            for (int j = 0; j <= DEG - i; j++) { scoef[r] = rsqrtf(fact[i] * fact[j]); r++; }
    }
    __syncthreads();
    int n = blockIdx.x * blockDim.x + tid;
    float fa = fp[n] * (1.0f / BETA);
    float fb = fp[Nn + n] * (1.0f / BETA);
    float e = __expf(-0.5f * (fa * fa + fb * fb));
    g_e[n] = e;
    // phi_r = coef * fa^i * fb^j, enumerated (i outer, j inner), i+j<=DEG
    float pai = 1.f;
    int r = 0;
    for (int i = 0; i <= DEG; i++) {
        float pbj = 1.f;
        for (int j = 0; j <= DEG - i; j++) {
            g_phi[r][n] = scoef[r] * pai * pbj;
            pbj *= fb;
            r++;
        }
        pai *= fa;
    }
    // q0 = softmax over channels
    float l0 = lu[0 * Nn + n], l1 = lu[1 * Nn + n];
    float l2 = lu[2 * Nn + n], l3 = lu[3 * Nn + n];
    float mx = fmaxf(fmaxf(l0, l1), fmaxf(l2, l3));
    float e0 = __expf(l0 - mx), e1 = __expf(l1 - mx);
    float e2 = __expf(l2 - mx), e3 = __expf(l3 - mx);
    float inv = 1.0f / (e0 + e1 + e2 + e3);
    g_qp[0][0][n] = e0 * inv;
    g_qp[0][1][n] = e1 * inv;
    g_qp[0][2][n] = e2 * inv;
    g_qp[0][3][n] = e3 * inv;
}

// ----------------------------------------------- separable 3D conv per (rank,channel)
// phase 0: rowsum pass   (grid RK):   in = phi_r*e,        out = phi_r*conv
// phase 1: iteration     (grid NBLK): bilateral blocks r<RK: in/out mul = phi_r*pre1*q / phi_r*pre1
//                                     spatial  blocks r==RK: in/out mul = pre2*q / pre2
__global__ __launch_bounds__(1024) void k_conv(int phase, int qsel) {
    extern __shared__ float sm[];
    float* s_a = sm;
    float* s_b = sm + Nn;
    float* tx  = sm + 2 * Nn;
    float* ty  = tx + Xd;

    int tid = threadIdx.x;
    int b = blockIdx.x;
    int r, c;
    bool sp;
    if (phase == 0) { r = b; c = 0; sp = false; }
    else            { r = b >> 2; c = b & 3; sp = (r == RK); }
    int r_eff = sp ? 0 : r;

    if (tid < Xd) tx[tid] = sp ? g_gx[tid] : g_ax[tid];
    if (tid < Yd) ty[tid] = sp ? g_gyz[tid] : g_ayz[tid];

    // ---- load stage: s_a[p] = input multiplier
    {
        const float4* phi4  = (const float4*)g_phi[r_eff];
        const float4* pre14 = (const float4*)g_pre1;
        const float4* pre24 = (const float4*)g_pre2;
        const float4* e4    = (const float4*)g_e;
        const float4* q4    = (const float4*)g_qp[qsel][c];
        float4* sa4 = (float4*)s_a;
#pragma unroll
        for (int u = 0; u < 2; u++) {
            int i4 = tid * 2 + u;
            float4 w;
            if (phase == 0) {
                float4 A = phi4[i4], E = e4[i4];
                w = make_float4(A.x * E.x, A.y * E.y, A.z * E.z, A.w * E.w);
            } else if (!sp) {
                float4 A = phi4[i4], P = pre14[i4], Q = q4[i4];
                w = make_float4(A.x * P.x * Q.x, A.y * P.y * Q.y,
                                A.z * P.z * Q.z, A.w * P.w * Q.w);
            } else {
                float4 P = pre24[i4], Q = q4[i4];
                w = make_float4(P.x * Q.x, P.y * Q.y, P.z * Q.z, P.w * Q.w);
            }
            sa4[i4] = w;
        }
    }
    __syncthreads();

    // ---- conv-x: s_a -> s_b   (32 taps, stride 256); 4 outputs per thread
    {
        int warp = tid >> 5, lane = tid & 31;
        int xg = (warp >> 2) << 2;                  // xo base
        int yz = ((warp & 3) << 6) + (lane << 1);   // 2 consecutive yz per lane
        float2 acc[4] = {{0.f,0.f},{0.f,0.f},{0.f,0.f},{0.f,0.f}};
#pragma unroll
        for (int xp = 0; xp < Xd; xp++) {
            float2 v = *(const float2*)(s_a + (xp << 8) + yz);
#pragma unroll
            for (int k = 0; k < 4; k++) {
                float w = tx[abs(xg + k - xp)];
                acc[k].x += w * v.x;
                acc[k].y += w * v.y;
            }
        }
#pragma unroll
        for (int k = 0; k < 4; k++)
            *(float2*)(s_b + ((xg + k) << 8) + yz) = acc[k];
    }
    __syncthreads();

    // ---- conv-y: s_b -> s_a   (16 taps, stride 16); 4 outputs per thread
    {
        int warp = tid >> 5, lane = tid & 31;
        int yg = (warp >> 3) << 2;                   // yo base
        int idx = ((warp & 7) << 6) + (lane << 1);   // (x,z) pair index, 2 per lane
        int base = ((idx >> 4) << 8) + (idx & 15);
        float2 acc[4] = {{0.f,0.f},{0.f,0.f},{0.f,0.f},{0.f,0.f}};
#pragma unroll
        for (int yp = 0; yp < Yd; yp++) {
            float2 v = *(const float2*)(s_b + base + (yp << 4));
#pragma unroll
            for (int k = 0; k < 4; k++) {
                float w = ty[abs(yg + k - yp)];
                acc[k].x += w * v.x;
                acc[k].y += w * v.y;
            }
        }
#pragma unroll
        for (int k = 0; k < 4; k++)
            *(float2*)(s_a + base + ((yg + k) << 4)) = acc[k];
    }
    __syncthreads();

    // ---- conv-z: s_a -> s_b   (16 taps, stride 1); one (x,y)-line per thread
    {
        float tr[16];
#pragma unroll
        for (int i = 0; i < 16; i++) tr[i] = ty[i];
        if (tid < 512) {
            float l[16];
            const float4* L4 = (const float4*)(s_a + tid * 16);
#pragma unroll
            for (int i = 0; i < 4; i++) {
                float4 v = L4[i];
                l[4*i] = v.x; l[4*i+1] = v.y; l[4*i+2] = v.z; l[4*i+3] = v.w;
            }
            float o[16];
#pragma unroll
            for (int zo = 0; zo < 16; zo++) {
                float s = 0.f;
#pragma unroll
                for (int zp = 0; zp < 16; zp++)
                    s += tr[(zo > zp) ? (zo - zp) : (zp - zo)] * l[zp];
                o[zo] = s;
            }
            float4* O4 = (float4*)(s_b + tid * 16);
#pragma unroll
            for (int i = 0; i < 4; i++)
                O4[i] = make_float4(o[4*i], o[4*i+1], o[4*i+2], o[4*i+3]);
        }
    }
    __syncthreads();

    // ---- out stage: g_part[b][p] = out multiplier * conv result
    {
        const float4* phi4  = (const float4*)g_phi[r_eff];
        const float4* pre14 = (const float4*)g_pre1;
        const float4* pre24 = (const float4*)g_pre2;
        const float4* sb4   = (const float4*)s_b;
        float4* dst = (float4*)g_part[b];
#pragma unroll
        for (int u = 0; u < 2; u++) {
            int i4 = tid * 2 + u;
            float4 V = sb4[i4];
            float4 w;
            if (phase == 0) {
                float4 A = phi4[i4];
                w = make_float4(A.x * V.x, A.y * V.y, A.z * V.z, A.w * V.w);
            } else if (!sp) {
                float4 A = phi4[i4], P = pre14[i4];
                w = make_float4(A.x * P.x * V.x, A.y * P.y * V.y,
                                A.z * P.z * V.z, A.w * P.w * V.w);
            } else {
                float4 P = pre24[i4];
                w = make_float4(P.x * V.x, P.y * V.y, P.z * V.z, P.w * V.w);
            }
            dst[i4] = w;
        }
    }
}

// ------------------------------------------------------ normalization scales
__global__ void k_scales() {
    int n = blockIdx.x * blockDim.x + threadIdx.x;
    float s = 0.f;
#pragma unroll
    for (int r = 0; r < RK; r++) s += g_part[r][n];
    float rs1 = g_e[n] * s;                      // bilateral rowsum
    g_pre1[n] = sqrtf(W1c) * g_e[n] * rsqrtf(rs1);
    int x = n >> 8, y = (n >> 4) & 15, z = n & 15;
    g_pre2[n] = sqrtf(W2c) * rsqrtf(g_Rx[x] * g_Ryz[y] * g_Ryz[z]);
}

// --------------------------------------- reduce partials, compat, softmax update
__global__ void k_update(const float* __restrict__ lu, const float* __restrict__ comp,
                         int qdst, float* __restrict__ out) {
    __shared__ float sc[16];
    int tid = threadIdx.x;
    if (tid < 16) sc[tid] = comp[tid];
    __syncthreads();
    int n = blockIdx.x * blockDim.x + tid;

    float u[4];
#pragma unroll
    for (int c = 0; c < 4; c++) {
        float s = 0.f;
#pragma unroll
        for (int k = 0; k < RK + 1; k++) s += g_part[k * Cc + c][n];
        u[c] = s;
    }
    float lg[4];
#pragma unroll
    for (int o = 0; o < 4; o++) {
        float qu = sc[o * 4 + 0] * u[0] + sc[o * 4 + 1] * u[1]
                 + sc[o * 4 + 2] * u[2] + sc[o * 4 + 3] * u[3];
        lg[o] = lu[o * Nn + n] - qu;
    }
    float mx = fmaxf(fmaxf(lg[0], lg[1]), fmaxf(lg[2], lg[3]));
    float e0 = __expf(lg[0] - mx), e1 = __expf(lg[1] - mx);
    float e2 = __expf(lg[2] - mx), e3 = __expf(lg[3] - mx);
    float inv = 1.0f / (e0 + e1 + e2 + e3);
    float q0 = e0 * inv, q1 = e1 * inv, q2 = e2 * inv, q3 = e3 * inv;
    if (out) {
        out[0 * Nn + n] = q0;
        out[1 * Nn + n] = q1;
        out[2 * Nn + n] = q2;
        out[3 * Nn + n] = q3;
    } else {
        g_qp[qdst][0][n] = q0;
        g_qp[qdst][1][n] = q1;
        g_qp[qdst][2][n] = q2;
        g_qp[qdst][3][n] = q3;
    }
}

extern "C" void kernel_launch(void* const* d_in, const int* in_sizes, int n_in,
                              void* d_out, int out_size) {
    const float* lu   = (const float*)d_in[0];
    const float* fp   = (const float*)d_in[1];
    const float* comp = (const float*)d_in[2];
    float* out = (float*)d_out;

    cudaFuncSetAttribute(k_conv, cudaFuncAttributeMaxDynamicSharedMemorySize, SMEM_BYTES);

    k_tables<<<1, 64>>>();
    k_feat<<<Nn / 256, 256>>>(lu, fp);
    k_conv<<<RK, 1024, SMEM_BYTES>>>(0, 0);      // bilateral rowsums
    k_scales<<<Nn / 256, 256>>>();
    for (int it = 0; it < NITER; it++) {
        k_conv<<<NBLK, 1024, SMEM_BYTES>>>(1, it & 1);
        k_update<<<Nn / 256, 256>>>(lu, comp, (it + 1) & 1,
                                    (it == NITER - 1) ? out : nullptr);
    }
}

// round 3
// speedup vs baseline: 9.0993x; 1.1528x over previous
#include <cuda_runtime.h>
#include <math.h>

#define Xd 32
#define Yd 16
#define Nn 8192          // 32*16*16
#define Cc 4
#define NITER 5
#define ALPHA 5.0f
#define BETA  5.0f
#define GAMMA 5.0f
#define DEG 7            // total-degree Taylor truncation for exp(f.f')
#define RK 36            // #(i,j), i+j<=7
#define NBLK (RK * Cc + Cc)   // 148 == one block per SM (GB300 has 152)
#define SMEM_FLOATS (2 * Nn + 128)
#define SMEM_BYTES (SMEM_FLOATS * 4)

// ---- static device scratch (no allocations anywhere) ----
__device__ float g_phi[RK][Nn];      // phi, scaled in-place to psi = phi*pre1
__device__ float g_e[Nn];
__device__ float g_pre1[Nn];
__device__ float g_pre2[Nn];
__device__ float g_part[NBLK][Nn];   // per-(rank,channel) partials
__device__ float g_q[2][Cc][Nn];     // q ping-pong, planar
__device__ unsigned g_cnt;           // barrier arrival counter (self-resetting)
__device__ unsigned g_gen;           // barrier generation (monotonic, wrap-safe)

// ---- software grid barrier (all NBLK blocks guaranteed co-resident) ----
__device__ __forceinline__ void gbar() {
    __syncthreads();
    if (threadIdx.x == 0) {
        __threadfence();
        unsigned gen = atomicAdd(&g_gen, 0u);
        if (atomicAdd(&g_cnt, 1u) == NBLK - 1) {
            atomicExch(&g_cnt, 0u);
            __threadfence();
            atomicAdd(&g_gen, 1u);
        } else {
            while (atomicAdd(&g_gen, 0u) == gen) __nanosleep(100);
        }
        __threadfence();
    }
    __syncthreads();
}

// ---- separable 3D Gaussian conv over the 32x16x16 field in shared memory ----
// input in sa, result in sb (sa clobbered)
__device__ __forceinline__ void conv3d(float* sa, float* sb,
                                       const float* wx, const float* wyz, int tid) {
    __syncthreads();
    // conv-x: sa -> sb (32 taps, stride 256). Rolling weight registers.
    {
        int warp = tid >> 5, lane = tid & 31;
        int xg = (warp >> 2) << 2;
        int yz = ((warp & 3) << 6) + (lane << 1);
        float2 a0 = {0.f,0.f}, a1 = {0.f,0.f}, a2 = {0.f,0.f}, a3 = {0.f,0.f};
        float w0 = wx[xg], w1 = wx[xg + 1], w2 = wx[xg + 2], w3 = wx[xg + 3];
#pragma unroll
        for (int xp = 0; xp < Xd; xp++) {
            float2 v = *(const float2*)(sa + (xp << 8) + yz);
            a0.x += w0 * v.x; a0.y += w0 * v.y;
            a1.x += w1 * v.x; a1.y += w1 * v.y;
            a2.x += w2 * v.x; a2.y += w2 * v.y;
            a3.x += w3 * v.x; a3.y += w3 * v.y;
            if (xp < Xd - 1) {
                w3 = w2; w2 = w1; w1 = w0;
                int d = xg - xp - 1;
                w0 = wx[d < 0 ? -d : d];
            }
        }
        *(float2*)(sb + ((xg + 0) << 8) + yz) = a0;
        *(float2*)(sb + ((xg + 1) << 8) + yz) = a1;
        *(float2*)(sb + ((xg + 2) << 8) + yz) = a2;
        *(float2*)(sb + ((xg + 3) << 8) + yz) = a3;
    }
    __syncthreads();
    // conv-y: sb -> sa (16 taps, stride 16). 2 threads per y-line, regs, no conflicts.
    {
        int line = tid >> 1, half = tid & 1;
        int z = line & 15, x = line >> 4;
        int base = (x << 8) + z;
        float lin[16], wv[16];
#pragma unroll
        for (int y = 0; y < Yd; y++) lin[y] = sb[base + (y << 4)];
#pragma unroll
        for (int d = 0; d < Yd; d++) wv[d] = wyz[d];
        if (half == 0) {
#pragma unroll
            for (int yo = 0; yo < 8; yo++) {
                float s = 0.f;
#pragma unroll
                for (int yp = 0; yp < Yd; yp++)
                    s += wv[(yo > yp) ? (yo - yp) : (yp - yo)] * lin[yp];
                sa[base + (yo << 4)] = s;
            }
        } else {
#pragma unroll
            for (int yo = 8; yo < 16; yo++) {
                float s = 0.f;
#pragma unroll
                for (int yp = 0; yp < Yd; yp++)
                    s += wv[(yo > yp) ? (yo - yp) : (yp - yo)] * lin[yp];
                sa[base + (yo << 4)] = s;
            }
        }
    }
    __syncthreads();
    // conv-z: sa -> sb (16 taps, stride 1). 2 threads per z-line, float4 I/O.
    {
        int line = tid >> 1, half = tid & 1;
        float l[16], wv[16];
        const float4* L4 = (const float4*)(sa + line * 16);
#pragma unroll
        for (int i = 0; i < 4; i++) {
            float4 v = L4[i];
            l[4*i] = v.x; l[4*i+1] = v.y; l[4*i+2] = v.z; l[4*i+3] = v.w;
        }
#pragma unroll
        for (int d = 0; d < Yd; d++) wv[d] = wyz[d];
        float o[8];
        if (half == 0) {
#pragma unroll
            for (int zo = 0; zo < 8; zo++) {
                float s = 0.f;
#pragma unroll
                for (int zp = 0; zp < 16; zp++)
                    s += wv[(zo > zp) ? (zo - zp) : (zp - zo)] * l[zp];
                o[zo] = s;
            }
        } else {
#pragma unroll
            for (int zo = 8; zo < 16; zo++) {
                float s = 0.f;
#pragma unroll
                for (int zp = 0; zp < 16; zp++)
                    s += wv[(zo > zp) ? (zo - zp) : (zp - zo)] * l[zp];
                o[zo - 8] = s;
            }
        }
        float4* O4 = (float4*)(sb + line * 16 + half * 8);
        O4[0] = make_float4(o[0], o[1], o[2], o[3]);
        O4[1] = make_float4(o[4], o[5], o[6], o[7]);
    }
    __syncthreads();
}

__global__ __launch_bounds__(1024, 1) void k_crf(
    const float* __restrict__ lu, const float* __restrict__ fp,
    const float* __restrict__ comp, float* __restrict__ out) {
    extern __shared__ float sm[];
    float* s_a   = sm;
    float* s_b   = sm + Nn;
    float* s_wax = sm + 2 * Nn;        // 32: bilateral x-taps
    float* s_way = s_wax + 32;         // 16: bilateral y/z-taps
    float* s_wgx = s_way + 16;         // 32: spatial x-taps
    float* s_wgy = s_wgx + 32;         // 16: spatial y/z-taps
    float* s_cmp = s_wgy + 16;         // 16: compatibility

    int tid = threadIdx.x;
    int b = blockIdx.x;

    if (tid < 32) {
        float d2 = (float)tid * (float)tid;
        s_wax[tid] = __expf(-0.5f * d2 / (ALPHA * ALPHA));
        s_wgx[tid] = __expf(-0.5f * d2 / (GAMMA * GAMMA));
    }
    if (tid < 16) {
        float d2 = (float)tid * (float)tid;
        s_way[tid] = __expf(-0.5f * d2 / (ALPHA * ALPHA));
        s_wgy[tid] = __expf(-0.5f * d2 / (GAMMA * GAMMA));
        s_cmp[tid] = comp[tid];
    }
    __syncthreads();

    // ---- phase A: features, phi basis, q0 = softmax(lu) ----
    if (b < 8) {
        int n = (b << 10) + tid;
        float fa = fp[n] * (1.0f / BETA);
        float fb = fp[Nn + n] * (1.0f / BETA);
        float e = __expf(-0.5f * (fa * fa + fb * fb));
        g_e[n] = e;
        float fi = 1.f, pai = 1.f;
        int r = 0;
#pragma unroll
        for (int i = 0; i <= DEG; i++) {
            if (i > 0) fi *= (float)i;
            float fj = 1.f, pbj = 1.f;
#pragma unroll
            for (int j = 0; j <= DEG - i; j++) {
                if (j > 0) fj *= (float)j;
                g_phi[r][n] = rsqrtf(fi * fj) * pai * pbj;
                pbj *= fb;
                r++;
            }
            pai *= fa;
        }
        float l0 = lu[n], l1 = lu[Nn + n], l2 = lu[2 * Nn + n], l3 = lu[3 * Nn + n];
        float mx = fmaxf(fmaxf(l0, l1), fmaxf(l2, l3));
        float e0 = __expf(l0 - mx), e1 = __expf(l1 - mx);
        float e2 = __expf(l2 - mx), e3 = __expf(l3 - mx);
        float inv = 1.0f / (e0 + e1 + e2 + e3);
        g_q[0][0][n] = e0 * inv; g_q[0][1][n] = e1 * inv;
        g_q[0][2][n] = e2 * inv; g_q[0][3][n] = e3 * inv;
    }
    gbar();

    // ---- phase B: bilateral rowsums (blocks 0..RK-1, rank b) ----
    if (b < RK) {
        const float4* phi4 = (const float4*)g_phi[b];
        const float4* e4 = (const float4*)g_e;
        float4* sa4 = (float4*)s_a;
#pragma unroll
        for (int u = 0; u < 2; u++) {
            int i4 = tid * 2 + u;
            float4 A = phi4[i4], E = e4[i4];
            sa4[i4] = make_float4(A.x * E.x, A.y * E.y, A.z * E.z, A.w * E.w);
        }
        conv3d(s_a, s_b, s_wax, s_way, tid);
        const float4* sb4 = (const float4*)s_b;
        float4* dst = (float4*)g_part[b];
#pragma unroll
        for (int u = 0; u < 2; u++) {
            int i4 = tid * 2 + u;
            float4 A = phi4[i4], V = sb4[i4];
            dst[i4] = make_float4(A.x * V.x, A.y * V.y, A.z * V.z, A.w * V.w);
        }
    }
    gbar();

    // ---- phase C: normalization scales ----
    if (b < 8) {
        int n = (b << 10) + tid;
        float s = 0.f;
#pragma unroll
        for (int r = 0; r < RK; r++) s += g_part[r][n];
        float e = g_e[n];
        g_pre1[n] = e * rsqrtf(e * s);
        int x = n >> 8, y = (n >> 4) & 15, z = n & 15;
        float Rx = 0.f, Ry = 0.f, Rz = 0.f;
#pragma unroll
        for (int d = 0; d < Xd; d++) Rx += s_wgx[(x > d) ? (x - d) : (d - x)];
#pragma unroll
        for (int d = 0; d < Yd; d++) {
            Ry += s_wgy[(y > d) ? (y - d) : (d - y)];
            Rz += s_wgy[(z > d) ? (z - d) : (d - z)];
        }
        g_pre2[n] = rsqrtf(Rx * Ry * Rz);
    }
    gbar();

    // ---- phase D: psi = phi * pre1 (in place) ----
    if (b < RK) {
#pragma unroll
        for (int u = 0; u < 8; u++) {
            int n = (u << 10) + tid;
            g_phi[b][n] *= g_pre1[n];
        }
    }
    gbar();

    // ---- phase E: 5 mean-field iterations ----
    int r = b >> 2, c = b & 3;
    bool sp = (r == RK);
    const float4* mul4 = sp ? (const float4*)g_pre2 : (const float4*)g_phi[r];
    for (int it = 0; it < NITER; it++) {
        // conv: all 148 blocks busy
        {
            const float4* q4 = (const float4*)g_q[it & 1][c];
            float4* sa4 = (float4*)s_a;
#pragma unroll
            for (int u = 0; u < 2; u++) {
                int i4 = tid * 2 + u;
                float4 M = mul4[i4], Q = q4[i4];
                sa4[i4] = make_float4(M.x * Q.x, M.y * Q.y, M.z * Q.z, M.w * Q.w);
            }
            conv3d(s_a, s_b, sp ? s_wgx : s_wax, sp ? s_wgy : s_way, tid);
            const float4* sb4 = (const float4*)s_b;
            float4* dst = (float4*)g_part[b];
#pragma unroll
            for (int u = 0; u < 2; u++) {
                int i4 = tid * 2 + u;
                float4 M = mul4[i4], V = sb4[i4];
                dst[i4] = make_float4(M.x * V.x, M.y * V.y, M.z * V.z, M.w * V.w);
            }
        }
        gbar();
        // update: reduce partials, compat, softmax
        if (b < 8) {
            int n = (b << 10) + tid;
            float u0 = 0.f, u1 = 0.f, u2 = 0.f, u3 = 0.f;
#pragma unroll
            for (int k = 0; k <= RK; k++) {
                u0 += g_part[k * 4 + 0][n];
                u1 += g_part[k * 4 + 1][n];
                u2 += g_part[k * 4 + 2][n];
                u3 += g_part[k * 4 + 3][n];
            }
            float lg[4];
#pragma unroll
            for (int o = 0; o < 4; o++) {
                float qu = s_cmp[o * 4 + 0] * u0 + s_cmp[o * 4 + 1] * u1
                         + s_cmp[o * 4 + 2] * u2 + s_cmp[o * 4 + 3] * u3;
                lg[o] = lu[o * Nn + n] - qu;
            }
            float mx = fmaxf(fmaxf(lg[0], lg[1]), fmaxf(lg[2], lg[3]));
            float e0 = __expf(lg[0] - mx), e1 = __expf(lg[1] - mx);
            float e2 = __expf(lg[2] - mx), e3 = __expf(lg[3] - mx);
            float inv = 1.0f / (e0 + e1 + e2 + e3);
            if (it == NITER - 1) {
                out[0 * Nn + n] = e0 * inv; out[1 * Nn + n] = e1 * inv;
                out[2 * Nn + n] = e2 * inv; out[3 * Nn + n] = e3 * inv;
            } else {
                int p = (it + 1) & 1;
                g_q[p][0][n] = e0 * inv; g_q[p][1][n] = e1 * inv;
                g_q[p][2][n] = e2 * inv; g_q[p][3][n] = e3 * inv;
            }
        }
        if (it < NITER - 1) gbar();
    }
}

extern "C" void kernel_launch(void* const* d_in, const int* in_sizes, int n_in,
                              void* d_out, int out_size) {
    const float* lu   = (const float*)d_in[0];
    const float* fp   = (const float*)d_in[1];
    const float* comp = (const float*)d_in[2];
    float* out = (float*)d_out;

    cudaFuncSetAttribute(k_crf, cudaFuncAttributeMaxDynamicSharedMemorySize, SMEM_BYTES);
    k_crf<<<NBLK, 1024, SMEM_BYTES>>>(lu, fp, comp, out);
}

// round 4
// speedup vs baseline: 11.1049x; 1.2204x over previous
#include <cuda_runtime.h>
#include <math.h>

#define Xd 32
#define Yd 16
#define Nn 8192          // 32*16*16
#define Cc 4
#define NITER 5
#define ALPHA 5.0f
#define BETA  5.0f
#define GAMMA 5.0f
#define DEG 7            // total-degree Taylor truncation for exp(f.f')
#define RK 36            // #(i,j), i+j<=7
#define NBLK (RK * Cc + Cc)   // 148 blocks == co-resident on 152 SMs
#define SMEM_FLOATS (2 * Nn + 160)
#define SMEM_BYTES (SMEM_FLOATS * 4)

// ---- static device scratch (no allocations anywhere) ----
__device__ float g_phi[RK][Nn];      // phi, scaled in place to psi = phi*pre1
__device__ float g_e[Nn];
__device__ float g_pre1[Nn];
__device__ float g_pre2[Nn];
__device__ float g_part[NBLK][Nn];   // per-(rank,channel) partials
__device__ float g_q[2][Cc][Nn];     // q ping-pong, planar
__device__ unsigned g_arr[NBLK];     // per-block arrival flags (monotonic)
__device__ unsigned g_gen;           // published generation (monotonic)

// ---- contention-free grid barrier: flag array + single observer block ----
__device__ __forceinline__ void gbar(unsigned tgt, int b, int tid) {
    __syncthreads();
    if (b == 0) {
        if (tid == 0) { __threadfence(); *(volatile unsigned*)&g_arr[0] = tgt; }
        if (tid < NBLK) {
            while (*(volatile unsigned*)&g_arr[tid] < tgt) { }
        }
        __syncthreads();
        if (tid == 0) { __threadfence(); *(volatile unsigned*)&g_gen = tgt; }
    } else {
        if (tid == 0) {
            __threadfence();
            *(volatile unsigned*)&g_arr[b] = tgt;
            while (*(volatile unsigned*)&g_gen < tgt) { }
            __threadfence();
        }
        __syncthreads();
    }
}

// ---- separable 3D Gaussian conv over 32x16x16 field in shared memory ----
// input sa, result sb (sa clobbered). All branches warp-uniform.
__device__ __forceinline__ void conv3d(float* sa, float* sb,
                                       const float* wx, const float* wyz, int tid) {
    __syncthreads();
    // conv-x: sa -> sb (32 taps, stride 256), rolling weight registers
    {
        int warp = tid >> 5, lane = tid & 31;
        int xg = (warp >> 2) << 2;
        int yz = ((warp & 3) << 6) + (lane << 1);
        float2 a0 = {0.f,0.f}, a1 = {0.f,0.f}, a2 = {0.f,0.f}, a3 = {0.f,0.f};
        float w0 = wx[xg], w1 = wx[xg + 1], w2 = wx[xg + 2], w3 = wx[xg + 3];
#pragma unroll
        for (int xp = 0; xp < Xd; xp++) {
            float2 v = *(const float2*)(sa + (xp << 8) + yz);
            a0.x += w0 * v.x; a0.y += w0 * v.y;
            a1.x += w1 * v.x; a1.y += w1 * v.y;
            a2.x += w2 * v.x; a2.y += w2 * v.y;
            a3.x += w3 * v.x; a3.y += w3 * v.y;
            if (xp < Xd - 1) {
                w3 = w2; w2 = w1; w1 = w0;
                int d = xg - xp - 1;
                w0 = wx[d < 0 ? -d : d];
            }
        }
        *(float2*)(sb + ((xg + 0) << 8) + yz) = a0;
        *(float2*)(sb + ((xg + 1) << 8) + yz) = a1;
        *(float2*)(sb + ((xg + 2) << 8) + yz) = a2;
        *(float2*)(sb + ((xg + 3) << 8) + yz) = a3;
    }
    __syncthreads();
    // conv-y: sb -> sa (16 taps, stride 16). 2 threads/line, half = tid>>9 (warp-uniform)
    {
        int line = tid & 511, half = tid >> 9;
        int z = line & 15, x = line >> 4;
        int base = (x << 8) + z;
        float lin[16], wv[16];
#pragma unroll
        for (int y = 0; y < Yd; y++) lin[y] = sb[base + (y << 4)];
#pragma unroll
        for (int d = 0; d < Yd; d++) wv[d] = wyz[d];
        if (half == 0) {
#pragma unroll
            for (int yo = 0; yo < 8; yo++) {
                float s = 0.f;
#pragma unroll
                for (int yp = 0; yp < Yd; yp++)
                    s += wv[(yo > yp) ? (yo - yp) : (yp - yo)] * lin[yp];
                sa[base + (yo << 4)] = s;
            }
        } else {
#pragma unroll
            for (int yo = 8; yo < 16; yo++) {
                float s = 0.f;
#pragma unroll
                for (int yp = 0; yp < Yd; yp++)
                    s += wv[(yo > yp) ? (yo - yp) : (yp - yo)] * lin[yp];
                sa[base + (yo << 4)] = s;
            }
        }
    }
    __syncthreads();
    // conv-z: sa -> sb (16 taps, stride 1). 2 threads/line, half = tid>>9
    {
        int line = tid & 511, half = tid >> 9;
        float l[16], wv[16];
        const float4* L4 = (const float4*)(sa + line * 16);
#pragma unroll
        for (int i = 0; i < 4; i++) {
            float4 v = L4[i];
            l[4*i] = v.x; l[4*i+1] = v.y; l[4*i+2] = v.z; l[4*i+3] = v.w;
        }
#pragma unroll
        for (int d = 0; d < Yd; d++) wv[d] = wyz[d];
        float o[8];
        if (half == 0) {
#pragma unroll
            for (int zo = 0; zo < 8; zo++) {
                float s = 0.f;
#pragma unroll
                for (int zp = 0; zp < 16; zp++)
                    s += wv[(zo > zp) ? (zo - zp) : (zp - zo)] * l[zp];
                o[zo] = s;
            }
        } else {
#pragma unroll
            for (int zo = 8; zo < 16; zo++) {
                float s = 0.f;
#pragma unroll
                for (int zp = 0; zp < 16; zp++)
                    s += wv[(zo > zp) ? (zo - zp) : (zp - zo)] * l[zp];
                o[zo - 8] = s;
            }
        }
        float4* O4 = (float4*)(sb + line * 16 + half * 8);
        O4[0] = make_float4(o[0], o[1], o[2], o[3]);
        O4[1] = make_float4(o[4], o[5], o[6], o[7]);
    }
    __syncthreads();
}

__global__ __launch_bounds__(1024, 1) void k_crf(
    const float* __restrict__ lu, const float* __restrict__ fp,
    const float* __restrict__ comp, float* __restrict__ out) {
    extern __shared__ float sm[];
    float* s_a   = sm;
    float* s_b   = sm + Nn;
    float* s_wax = sm + 2 * Nn;        // 32
    float* s_way = s_wax + 32;         // 16
    float* s_wgx = s_way + 16;         // 32
    float* s_wgy = s_wgx + 32;         // 16
    float* s_cmp = s_wgy + 16;         // 16
    __shared__ unsigned s_base;

    int tid = threadIdx.x;
    int b = blockIdx.x;

    if (tid == 0) s_base = *(volatile unsigned*)&g_arr[b];  // own flag: replay-safe base
    if (tid < 32) {
        float d2 = (float)tid * (float)tid;
        s_wax[tid] = __expf(-0.5f * d2 / (ALPHA * ALPHA));
        s_wgx[tid] = __expf(-0.5f * d2 / (GAMMA * GAMMA));
    }
    if (tid < 16) {
        float d2 = (float)tid * (float)tid;
        s_way[tid] = __expf(-0.5f * d2 / (ALPHA * ALPHA));
        s_wgy[tid] = __expf(-0.5f * d2 / (GAMMA * GAMMA));
        s_cmp[tid] = comp[tid];
    }
    __syncthreads();
    unsigned base = s_base, bk = 0;

    // ---- phase A: features, phi basis, q0 = softmax(lu) ----
    if (b < 8) {
        int n = (b << 10) + tid;
        float fa = fp[n] * (1.0f / BETA);
        float fb = fp[Nn + n] * (1.0f / BETA);
        float e = __expf(-0.5f * (fa * fa + fb * fb));
        g_e[n] = e;
        float fi = 1.f, pai = 1.f;
        int r = 0;
#pragma unroll
        for (int i = 0; i <= DEG; i++) {
            if (i > 0) fi *= (float)i;
            float fj = 1.f, pbj = 1.f;
#pragma unroll
            for (int j = 0; j <= DEG - i; j++) {
                if (j > 0) fj *= (float)j;
                g_phi[r][n] = rsqrtf(fi * fj) * pai * pbj;
                pbj *= fb;
                r++;
            }
            pai *= fa;
        }
        float l0 = lu[n], l1 = lu[Nn + n], l2 = lu[2 * Nn + n], l3 = lu[3 * Nn + n];
        float mx = fmaxf(fmaxf(l0, l1), fmaxf(l2, l3));
        float e0 = __expf(l0 - mx), e1 = __expf(l1 - mx);
        float e2 = __expf(l2 - mx), e3 = __expf(l3 - mx);
        float inv = 1.0f / (e0 + e1 + e2 + e3);
        g_q[0][0][n] = e0 * inv; g_q[0][1][n] = e1 * inv;
        g_q[0][2][n] = e2 * inv; g_q[0][3][n] = e3 * inv;
    }
    gbar(base + (++bk), b, tid);

    // ---- phase B: bilateral rowsums (blocks 0..RK-1) ----
    if (b < RK) {
        const float4* phi4 = (const float4*)g_phi[b];
        const float4* e4 = (const float4*)g_e;
        float4* sa4 = (float4*)s_a;
#pragma unroll
        for (int u = 0; u < 2; u++) {
            int i4 = tid * 2 + u;
            float4 A = phi4[i4], E = e4[i4];
            sa4[i4] = make_float4(A.x * E.x, A.y * E.y, A.z * E.z, A.w * E.w);
        }
        conv3d(s_a, s_b, s_wax, s_way, tid);
        const float4* sb4 = (const float4*)s_b;
        float4* dst = (float4*)g_part[b];
#pragma unroll
        for (int u = 0; u < 2; u++) {
            int i4 = tid * 2 + u;
            float4 A = phi4[i4], V = sb4[i4];
            dst[i4] = make_float4(A.x * V.x, A.y * V.y, A.z * V.z, A.w * V.w);
        }
    }
    gbar(base + (++bk), b, tid);

    // ---- phase C: normalization scales (distributed: 32 blocks x 256 threads) ----
    if (b < 32 && tid < 256) {
        int n = (b << 8) + tid;
        float s = 0.f;
#pragma unroll
        for (int r = 0; r < RK; r++) s += __ldcg(&g_part[r][n]);
        float e = g_e[n];
        g_pre1[n] = e * rsqrtf(e * s);
        int x = n >> 8, y = (n >> 4) & 15, z = n & 15;
        float Rx = 0.f, Ry = 0.f, Rz = 0.f;
#pragma unroll
        for (int d = 0; d < Xd; d++) Rx += s_wgx[(x > d) ? (x - d) : (d - x)];
#pragma unroll
        for (int d = 0; d < Yd; d++) {
            Ry += s_wgy[(y > d) ? (y - d) : (d - y)];
            Rz += s_wgy[(z > d) ? (z - d) : (d - z)];
        }
        g_pre2[n] = rsqrtf(Rx * Ry * Rz);
    }
    gbar(base + (++bk), b, tid);

    // ---- phase D: psi = phi * pre1 in place ----
    if (b < RK) {
#pragma unroll
        for (int u = 0; u < 8; u++) {
            int n = (u << 10) + tid;
            g_phi[b][n] *= g_pre1[n];
        }
    }
    gbar(base + (++bk), b, tid);

    // ---- phase E: 5 mean-field iterations ----
    int r = b >> 2, c = b & 3;
    bool sp = (r == RK);
    const float4* mul4 = sp ? (const float4*)g_pre2 : (const float4*)g_phi[r];
    const float* wxE = sp ? s_wgx : s_wax;
    const float* wyE = sp ? s_wgy : s_way;
    for (int it = 0; it < NITER; it++) {
        // conv: all 148 blocks busy
        {
            const float4* q4 = (const float4*)g_q[it & 1][c];
            float4* sa4 = (float4*)s_a;
#pragma unroll
            for (int u = 0; u < 2; u++) {
                int i4 = tid * 2 + u;
                float4 M = __ldcg(mul4 + i4);
                float4 Q = __ldcg(q4 + i4);
                sa4[i4] = make_float4(M.x * Q.x, M.y * Q.y, M.z * Q.z, M.w * Q.w);
            }
            conv3d(s_a, s_b, wxE, wyE, tid);
            const float4* sb4 = (const float4*)s_b;
            float4* dst = (float4*)g_part[b];
#pragma unroll
            for (int u = 0; u < 2; u++) {
                int i4 = tid * 2 + u;
                float4 M = __ldcg(mul4 + i4);
                float4 V = sb4[i4];
                dst[i4] = make_float4(M.x * V.x, M.y * V.y, M.z * V.z, M.w * V.w);
            }
        }
        gbar(base + (++bk), b, tid);
        // update (distributed): 128 blocks x 256 threads, one (n,c) per thread
        if (b < 128 && tid < 256) {
            int idx = (b << 8) + tid;
            int cc = idx & 3, n = idx >> 2;
            float u = 0.f;
#pragma unroll
            for (int k = 0; k <= RK; k++)
                u += __ldcg(&g_part[k * 4 + cc][n]);
            float v1 = __shfl_xor_sync(0xFFFFFFFFu, u, 1);
            float v2 = __shfl_xor_sync(0xFFFFFFFFu, u, 2);
            float v3 = __shfl_xor_sync(0xFFFFFFFFu, u, 3);
            float qu = s_cmp[cc * 4 + cc] * u
                     + s_cmp[cc * 4 + (cc ^ 1)] * v1
                     + s_cmp[cc * 4 + (cc ^ 2)] * v2
                     + s_cmp[cc * 4 + (cc ^ 3)] * v3;
            float lg = lu[cc * Nn + n] - qu;
            float m1 = fmaxf(lg, __shfl_xor_sync(0xFFFFFFFFu, lg, 1));
            float mx = fmaxf(m1, __shfl_xor_sync(0xFFFFFFFFu, m1, 2));
            float e = __expf(lg - mx);
            float s1 = e + __shfl_xor_sync(0xFFFFFFFFu, e, 1);
            float ss = s1 + __shfl_xor_sync(0xFFFFFFFFu, s1, 2);
            float qv = e / ss;
            if (it == NITER - 1) out[cc * Nn + n] = qv;
            else                 g_q[(it + 1) & 1][cc][n] = qv;
        }
        if (it < NITER - 1) gbar(base + (++bk), b, tid);
    }
}

extern "C" void kernel_launch(void* const* d_in, const int* in_sizes, int n_in,
                              void* d_out, int out_size) {
    const float* lu   = (const float*)d_in[0];
    const float* fp   = (const float*)d_in[1];
    const float* comp = (const float*)d_in[2];
    float* out = (float*)d_out;

    cudaFuncSetAttribute(k_crf, cudaFuncAttributeMaxDynamicSharedMemorySize, SMEM_BYTES);
    k_crf<<<NBLK, 1024, SMEM_BYTES>>>(lu, fp, comp, out);
}